// round 4
// baseline (speedup 1.0000x reference)
#include <cuda_runtime.h>
#include <cstdint>

// ===================== problem sizes =====================
#define TOKENS 8192      // B*S = 4*2048
#define HID    2048
#define IDIM   8192

// ===================== scratch (device globals; no allocation allowed) =====
__device__ float g_Y  [TOKENS * HID];          // 64 MB  LN output (tf32-rounded)
__device__ float g_W1t[2 * IDIM * HID];        // 128 MB W1^T [16384][2048] (tf32)
__device__ float g_W2t[HID * IDIM];            // 64 MB  W2^T [2048][8192]  (tf32)
__device__ float g_H  [TOKENS * 2 * IDIM];     // 512 MB GEMM1 output (fp32)
__device__ float g_Z  [TOKENS * IDIM];         // 256 MB GeGLU output (tf32)

// ===================== helpers =====================
__device__ __forceinline__ uint32_t smem_u32(const void* p) {
    uint32_t a;
    asm("{ .reg .u64 t; cvta.to.shared.u64 t, %1; cvt.u32.u64 %0, t; }" : "=r"(a) : "l"(p));
    return a;
}
__device__ __forceinline__ float rna_tf32(float f) {
    uint32_t u;
    asm("cvt.rna.tf32.f32 %0, %1;" : "=r"(u) : "f"(f));
    return __uint_as_float(u);
}
__device__ __forceinline__ void cp_async16(uint32_t dst, const void* src) {
    asm volatile("cp.async.cg.shared.global [%0], [%1], 16;" :: "r"(dst), "l"(src) : "memory");
}
__device__ __forceinline__ void cp_commit() {
    asm volatile("cp.async.commit_group;" ::: "memory");
}
template <int N>
__device__ __forceinline__ void cp_wait() {
    asm volatile("cp.async.wait_group %0;" :: "n"(N) : "memory");
}

// m16n8k8 tf32 MMA (fp32 accumulate), baseline sm_80 PTX — valid on compute_103.
__device__ __forceinline__ void mma_tf32(float* c, const uint32_t* a, const uint32_t* b) {
    asm volatile(
        "mma.sync.aligned.m16n8k8.row.col.f32.tf32.tf32.f32 "
        "{%0,%1,%2,%3}, {%4,%5,%6,%7}, {%8,%9}, {%0,%1,%2,%3};"
        : "+f"(c[0]), "+f"(c[1]), "+f"(c[2]), "+f"(c[3])
        : "r"(a[0]), "r"(a[1]), "r"(a[2]), "r"(a[3]), "r"(b[0]), "r"(b[1]));
}

// ===================== LayerNorm -> g_Y (tf32-rounded) =====================
__global__ void __launch_bounds__(256) ln_kernel(const float* __restrict__ x,
                                                 const float* __restrict__ scale,
                                                 const float* __restrict__ bias) {
    __shared__ float red1[8], red2[8];
    const int row = blockIdx.x;
    const int tid = threadIdx.x, wid = tid >> 5, lid = tid & 31;
    const float* xr = x + (size_t)row * HID;

    float v[8];
#pragma unroll
    for (int i = 0; i < 8; i++) v[i] = xr[tid + i * 256];

    float s1 = 0.f, s2 = 0.f;
#pragma unroll
    for (int i = 0; i < 8; i++) { s1 += v[i]; s2 += v[i] * v[i]; }
#pragma unroll
    for (int o = 16; o > 0; o >>= 1) {
        s1 += __shfl_xor_sync(0xFFFFFFFF, s1, o);
        s2 += __shfl_xor_sync(0xFFFFFFFF, s2, o);
    }
    if (lid == 0) { red1[wid] = s1; red2[wid] = s2; }
    __syncthreads();
    if (tid == 0) {
        float t1 = 0.f, t2 = 0.f;
#pragma unroll
        for (int i = 0; i < 8; i++) { t1 += red1[i]; t2 += red2[i]; }
        red1[0] = t1; red2[0] = t2;
    }
    __syncthreads();
    const float mu  = red1[0] * (1.0f / HID);
    const float var = red2[0] * (1.0f / HID) - mu * mu;
    const float inv = rsqrtf(var + 1e-6f);

    float* yr = g_Y + (size_t)row * HID;
#pragma unroll
    for (int i = 0; i < 8; i++) {
        const int c = tid + i * 256;
        yr[c] = rna_tf32((v[i] - mu) * inv * scale[c] + bias[c]);
    }
}

// ===================== transpose + tf32 round =====================
// in: [R][C] row-major  ->  out: [C][R] row-major
__global__ void __launch_bounds__(256) transpose_kernel(const float* __restrict__ in,
                                                        float* __restrict__ out,
                                                        int R, int C) {
    __shared__ float t[32][33];
    const int bx = blockIdx.x, by = blockIdx.y;
    const int tx = threadIdx.x, ty = threadIdx.y;   // (32, 8)
    const int x = bx * 32 + tx;
#pragma unroll
    for (int j = 0; j < 32; j += 8)
        t[ty + j][tx] = in[(size_t)(by * 32 + ty + j) * C + x];
    __syncthreads();
    const int ox = by * 32 + tx;
#pragma unroll
    for (int j = 0; j < 32; j += 8)
        out[(size_t)(bx * 32 + ty + j) * R + ox] = rna_tf32(t[tx][ty + j]);
}

// ===================== GeGLU: g_H -> g_Z (tf32-rounded) =====================
__global__ void __launch_bounds__(256) geglu_kernel() {
    const size_t i = (size_t)blockIdx.x * 256 + threadIdx.x;   // float4 index
    const size_t r  = i / (IDIM / 4);
    const size_t c4 = i % (IDIM / 4);
    const float4* H4 = (const float4*)g_H;
    const float4 a = H4[r * (2 * IDIM / 4) + c4];
    const float4 b = H4[r * (2 * IDIM / 4) + (IDIM / 4) + c4];
    float4 z;
    const float* ap = &a.x; const float* bp = &b.x; float* zp = &z.x;
#pragma unroll
    for (int j = 0; j < 4; j++) {
        const float av = ap[j];
        const float g = 0.5f * av *
            (1.0f + tanhf(0.7978845608028654f * (av + 0.044715f * av * av * av)));
        zp[j] = rna_tf32(g * bp[j]);
    }
    ((float4*)g_Z)[i] = z;
}

// ===================== tiled tf32 mma.sync GEMM =====================
// Block tile 128(M) x 256(N), K-chunk 32, 512 threads (16 warps, 4m x 4n),
// warp tile 32x64. 4-stage cp.async pipeline.
// MODE 0: out = g_Y[8192x2048] * g_W1t^T -> g_H (N=16384)
// MODE 1: out = g_Z[8192x8192] * g_W2t^T -> d_out (N=2048)
#define BM 128
#define BN 256
#define BK 32
#define PADK 36                     // floats per smem row (conflict-free)
#define A_BYTES (BM * PADK * 4)     // 18432
#define B_BYTES (BN * PADK * 4)     // 36864
#define STAGE_BYTES (A_BYTES + B_BYTES)
#define STAGES 4
#define SMEM_NEED (STAGES * STAGE_BYTES)   // 221184 B

template <int MODE>
__global__ void __launch_bounds__(512, 1) gemm_kernel(float* __restrict__ outp) {
    constexpr int K  = (MODE == 0) ? HID : IDIM;
    constexpr int NC = K / BK;
    constexpr int NN = (MODE == 0) ? 2 * IDIM : HID;
    constexpr int numBn = NN / BN;

    extern __shared__ char smem_raw[];
    const uint32_t sm = smem_u32(smem_raw);

    const int tid = threadIdx.x, wid = tid >> 5, lid = tid & 31;
    const int warp_m = wid & 3;       // 0..3 -> m strip of 32
    const int warp_n = wid >> 2;      // 0..3 -> n strip of 64
    const int g  = lid >> 2;          // 0..7
    const int tg = lid & 3;           // 0..3

    // supertile remap: groups of 8 m-tiles sweep bn together (L2 reuse)
    const int bid   = blockIdx.x;
    const int group = bid / (8 * numBn);
    const int rem   = bid % (8 * numBn);
    const int m0    = (group * 8 + (rem & 7)) * BM;
    const int n0    = (rem / 8) * BN;

    const float* __restrict__ A  = (MODE == 0) ? g_Y : g_Z;
    const float* __restrict__ Bw = (MODE == 0) ? g_W1t : g_W2t;
    float* __restrict__ C = (MODE == 0) ? g_H : outp;

    const float* Ag = A  + (size_t)m0 * K;
    const float* Bg = Bw + (size_t)n0 * K;

    // per-thread cp.async chunk assignment: 2 A chunks + 4 B chunks (16B each)
    const int ciA0 = tid,        ciA1 = tid + 512;            // A: 1024 chunks
    const int rA0 = ciA0 >> 3, chA0 = ciA0 & 7;
    const int rA1 = ciA1 >> 3, chA1 = ciA1 & 7;

    auto issue_stage = [&](int cc) {
        const uint32_t sd = sm + (cc & (STAGES - 1)) * STAGE_BYTES;
        const size_t kof = (size_t)cc * BK;
        cp_async16(sd + rA0 * (PADK * 4) + chA0 * 16, Ag + (size_t)rA0 * K + kof + chA0 * 4);
        cp_async16(sd + rA1 * (PADK * 4) + chA1 * 16, Ag + (size_t)rA1 * K + kof + chA1 * 4);
#pragma unroll
        for (int j = 0; j < 4; ++j) {
            const int ci = tid + j * 512;                      // B: 2048 chunks
            const int r = ci >> 3, ch = ci & 7;
            cp_async16(sd + A_BYTES + r * (PADK * 4) + ch * 16,
                       Bg + (size_t)r * K + kof + ch * 4);
        }
        cp_commit();
    };

    // prologue: fill 3 stages
#pragma unroll
    for (int s = 0; s < STAGES - 1; ++s) issue_stage(s);

    float acc[2][8][4];
#pragma unroll
    for (int mt = 0; mt < 2; ++mt)
#pragma unroll
        for (int nt = 0; nt < 8; ++nt)
#pragma unroll
            for (int q = 0; q < 4; ++q) acc[mt][nt][q] = 0.f;

    for (int c = 0; c < NC; ++c) {
        cp_wait<STAGES - 2>();
        __syncthreads();
        if (c + STAGES - 1 < NC) issue_stage(c + STAGES - 1);
        else cp_commit();   // keep group numbering aligned

        const char* sd = smem_raw + (c & (STAGES - 1)) * STAGE_BYTES;
        const uint32_t* As = (const uint32_t*)sd + (size_t)(warp_m * 32 + g) * PADK;
        const uint32_t* Bs = (const uint32_t*)(sd + A_BYTES) + (size_t)(warp_n * 64 + g) * PADK;

#pragma unroll
        for (int kk = 0; kk < 4; ++kk) {
            const int k0 = kk * 8 + tg;
            uint32_t a[2][4];
#pragma unroll
            for (int mt = 0; mt < 2; ++mt) {
                const uint32_t* ap = As + (size_t)mt * 16 * PADK;
                a[mt][0] = ap[k0];
                a[mt][1] = ap[8 * PADK + k0];
                a[mt][2] = ap[k0 + 4];
                a[mt][3] = ap[8 * PADK + k0 + 4];
            }
            uint32_t b[8][2];
#pragma unroll
            for (int nt = 0; nt < 8; ++nt) {
                const uint32_t* bp = Bs + (size_t)nt * 8 * PADK;
                b[nt][0] = bp[k0];
                b[nt][1] = bp[k0 + 4];
            }
#pragma unroll
            for (int mt = 0; mt < 2; ++mt)
#pragma unroll
                for (int nt = 0; nt < 8; ++nt)
                    mma_tf32(acc[mt][nt], a[mt], b[nt]);
        }
        __syncthreads();
    }

    // epilogue: float2 stores, 32B-aligned segments
#pragma unroll
    for (int mt = 0; mt < 2; ++mt) {
        const int r = m0 + warp_m * 32 + mt * 16 + g;
#pragma unroll
        for (int nt = 0; nt < 8; ++nt) {
            const int col = n0 + warp_n * 64 + nt * 8 + tg * 2;
            float2* d0 = (float2*)(C + (size_t)r * NN + col);
            float2* d1 = (float2*)(C + (size_t)(r + 8) * NN + col);
            *d0 = make_float2(acc[mt][nt][0], acc[mt][nt][1]);
            *d1 = make_float2(acc[mt][nt][2], acc[mt][nt][3]);
        }
    }
}

// ===================== launch =====================
extern "C" void kernel_launch(void* const* d_in, const int* in_sizes, int n_in,
                              void* d_out, int out_size) {
    const float* x     = (const float*)d_in[0];
    const float* scale = (const float*)d_in[1];
    const float* bias  = (const float*)d_in[2];
    const float* k1    = (const float*)d_in[3];   // [2048][16384]
    const float* k2    = (const float*)d_in[4];   // [8192][2048]
    float* out = (float*)d_out;

    float* w1t; cudaGetSymbolAddress((void**)&w1t, g_W1t);
    float* w2t; cudaGetSymbolAddress((void**)&w2t, g_W2t);

    cudaFuncSetAttribute(gemm_kernel<0>, cudaFuncAttributeMaxDynamicSharedMemorySize, SMEM_NEED);
    cudaFuncSetAttribute(gemm_kernel<1>, cudaFuncAttributeMaxDynamicSharedMemorySize, SMEM_NEED);

    // 1) LayerNorm -> g_Y
    ln_kernel<<<TOKENS, 256>>>(x, scale, bias);

    // 2) W1 [2048][16384] -> g_W1t [16384][2048]
    transpose_kernel<<<dim3(2 * IDIM / 32, HID / 32), dim3(32, 8)>>>(k1, w1t, HID, 2 * IDIM);

    // 3) W2 [8192][2048] -> g_W2t [2048][8192]
    transpose_kernel<<<dim3(HID / 32, IDIM / 32), dim3(32, 8)>>>(k2, w2t, IDIM, HID);

    // 4) GEMM1: g_Y * W1t^T -> g_H   (64 m-tiles x 64 n-tiles)
    gemm_kernel<0><<<64 * 64, 512, SMEM_NEED>>>(out);

    // 5) GeGLU: g_H -> g_Z
    geglu_kernel<<<(TOKENS * (IDIM / 4)) / 256, 256>>>();

    // 6) GEMM2: g_Z * W2t^T -> out  (64 m-tiles x 8 n-tiles)
    gemm_kernel<1><<<64 * 8, 512, SMEM_NEED>>>(out);
}